// round 1
// baseline (speedup 1.0000x reference)
#include <cuda_runtime.h>
#include <cstddef>

// Problem dims
#define B   512
#define T   512
#define IN  128
#define H   256
#define H3  768
#define OUT 128
#define BT  (B * T)

// ---------------------------------------------------------------------------
// Static device scratch (allowed: module-load allocation, not runtime alloc)
// ---------------------------------------------------------------------------
__device__ float g_IG[(size_t)BT * H3];   // 805 MB: precomputed input gates, [t][b][j]
__device__ float g_WihT[IN * H3];         // W_ih transposed: [k][j]
__device__ float g_WhhT[H * H3];          // W_hh transposed: [k][j]
__device__ float g_WLt[H * OUT];          // w_lin transposed: [k][o]
__device__ float g_h[2][B * H];           // ping-pong hidden state

// ---------------------------------------------------------------------------
// Packed fp32x2 helpers (Blackwell: FFMA 3-reg is half-rate; f32x2 restores it)
// ---------------------------------------------------------------------------
__device__ __forceinline__ void fma2(unsigned long long &acc,
                                     unsigned long long a,
                                     unsigned long long b) {
    asm("fma.rn.f32x2 %0, %1, %2, %0;" : "+l"(acc) : "l"(a), "l"(b));
}
__device__ __forceinline__ unsigned long long bcast2(float x) {
    unsigned long long r;
    asm("mov.b64 %0, {%1, %1};" : "=l"(r) : "f"(x));
    return r;
}
__device__ __forceinline__ float2 unpack2(unsigned long long v) {
    float2 f;
    asm("mov.b64 {%0, %1}, %2;" : "=f"(f.x), "=f"(f.y) : "l"(v));
    return f;
}

__device__ __forceinline__ float sigmoidf_(float x) {
    // exact enough: MUFU.EX2 + MUFU.RCP path; safe at +/-inf
    return __fdividef(1.0f, 1.0f + __expf(-x));
}
__device__ __forceinline__ float tanhf_(float x) {
    // tanh(x) = 2*sigmoid(2x) - 1 ; avoids inf/inf NaN of (1-e)/(1+e)
    return __fdividef(2.0f, 1.0f + __expf(-2.0f * x)) - 1.0f;
}

// ---------------------------------------------------------------------------
// Prep: transpose weights to k-major (coalesced step-kernel reads), zero h0
// ---------------------------------------------------------------------------
__global__ void prep_kernel(const float* __restrict__ w_ih,
                            const float* __restrict__ w_hh,
                            const float* __restrict__ w_lin) {
    int i = blockIdx.x * blockDim.x + threadIdx.x;
    if (i < IN * H3) {                 // w_ih: (H3, IN) row-major -> [k][j]
        int j = i / IN, k = i % IN;
        g_WihT[k * H3 + j] = w_ih[i];
    }
    if (i < H * H3) {                  // w_hh: (H3, H) -> [k][j]
        int j = i / H, k = i % H;
        g_WhhT[k * H3 + j] = w_hh[i];
    }
    if (i < OUT * H) {                 // w_lin: (OUT, H) -> [k][o]
        int o = i / H, k = i % H;
        g_WLt[k * OUT + o] = w_lin[i];
    }
    if (i < B * H) g_h[0][i] = 0.0f;   // h0 = zeros, every call (deterministic)
}

// ---------------------------------------------------------------------------
// IG GEMM: g_IG[t][b][j] = x[b][t][:] . w_ih[j][:] + bias_g[j]
// Tile: 32 bt-rows x 64 j-cols, K=128 in one shot. 256 threads.
// ---------------------------------------------------------------------------
__global__ __launch_bounds__(256) void ig_gemm(const float* __restrict__ x,
                                               const float* __restrict__ bias_g) {
    __shared__ float Xs[32 * IN];   // 16 KB, row-major [row][k]
    __shared__ float Ws[IN * 64];   // 32 KB, k-major  [k][jj]
    int tid = threadIdx.x;
    int bt0 = blockIdx.y * 32;
    int j0  = blockIdx.x * 64;

    // Load X tile (32x128 contiguous floats) — fully coalesced float4 copy
    {
        const float4* src = (const float4*)(x + (size_t)bt0 * IN);
        float4* dst = (float4*)Xs;
        #pragma unroll
        for (int i = 0; i < 4; i++) dst[tid + i * 256] = src[tid + i * 256];
    }
    // Load W tile from pre-transposed g_WihT: rows k, cols j0..j0+63
    {
        #pragma unroll
        for (int i = 0; i < 8; i++) {
            int f = tid + i * 256;
            int k = f >> 4, j4 = (f & 15) << 2;
            *(float4*)&Ws[k * 64 + j4] =
                *(const float4*)&g_WihT[k * H3 + j0 + j4];
        }
    }
    __syncthreads();

    int c = tid & 15;   // 4 cols: 4c..4c+3 (two f32x2 pairs)
    int r = tid >> 4;   // 2 rows: 2r, 2r+1
    unsigned long long acc[2][2] = {{0ULL, 0ULL}, {0ULL, 0ULL}};

    #pragma unroll 4
    for (int k = 0; k < IN; k++) {
        float x0 = Xs[(2 * r) * IN + k];       // LDS broadcast
        float x1 = Xs[(2 * r + 1) * IN + k];
        ulonglong2 w = *(const ulonglong2*)&Ws[k * 64 + 4 * c];  // LDS.128
        unsigned long long px0 = bcast2(x0), px1 = bcast2(x1);
        fma2(acc[0][0], px0, w.x); fma2(acc[0][1], px0, w.y);
        fma2(acc[1][0], px1, w.x); fma2(acc[1][1], px1, w.y);
    }

    float bg0 = bias_g[j0 + 4 * c + 0];
    float bg1 = bias_g[j0 + 4 * c + 1];
    float bg2 = bias_g[j0 + 4 * c + 2];
    float bg3 = bias_g[j0 + 4 * c + 3];
    #pragma unroll
    for (int rr = 0; rr < 2; rr++) {
        int bt = bt0 + 2 * r + rr;
        int b = bt >> 9;          // bt = b*T + t, T = 512
        int t = bt & (T - 1);
        float2 lo = unpack2(acc[rr][0]);
        float2 hi = unpack2(acc[rr][1]);
        float4 out = make_float4(lo.x + bg0, lo.y + bg1, hi.x + bg2, hi.y + bg3);
        *(float4*)&g_IG[((size_t)t * B + b) * H3 + j0 + 4 * c] = out;
    }
}

// ---------------------------------------------------------------------------
// One GRU timestep: hg = h @ W_hh^T fused with gate math.
// Tile: 32 batch rows x 32 h-cols (=> 96 gate cols r/z/n), grid (8,16)=128 CTAs.
// ---------------------------------------------------------------------------
__global__ __launch_bounds__(256) void gru_step(int t, const float* __restrict__ bias_n) {
    __shared__ float hs[32 * H];   // 32 KB: 32 rows of full h (256 cols)
    int tid = threadIdx.x;
    const float* __restrict__ h_in = g_h[t & 1];
    float* __restrict__ h_out = g_h[(t + 1) & 1];
    int row0 = blockIdx.y * 32;
    int j0   = blockIdx.x * 32;

    // Load h tile (32x256 contiguous) — coalesced float4 copy
    {
        const float4* src = (const float4*)(h_in + (size_t)row0 * H);
        float4* dst = (float4*)hs;
        #pragma unroll
        for (int i = 0; i < 8; i++) dst[tid + i * 256] = src[tid + i * 256];
    }
    __syncthreads();

    int c = tid & 15;        // col pair: j0 + 2c, 2c+1
    int r = tid >> 4;        // rows 2r, 2r+1
    int col = j0 + 2 * c;

    unsigned long long accR[2] = {0ULL, 0ULL};
    unsigned long long accZ[2] = {0ULL, 0ULL};
    unsigned long long accN[2] = {0ULL, 0ULL};
    const float* __restrict__ WtBase = g_WhhT + col;

    #pragma unroll 4
    for (int k = 0; k < H; k++) {
        unsigned long long h0 = bcast2(hs[(2 * r) * H + k]);       // LDS broadcast
        unsigned long long h1 = bcast2(hs[(2 * r + 1) * H + k]);
        const float* wrow = WtBase + (size_t)k * H3;
        unsigned long long wr = *(const unsigned long long*)(wrow);          // LDG.64 coalesced
        unsigned long long wz = *(const unsigned long long*)(wrow + H);
        unsigned long long wn = *(const unsigned long long*)(wrow + 2 * H);
        fma2(accR[0], h0, wr); fma2(accR[1], h1, wr);
        fma2(accZ[0], h0, wz); fma2(accZ[1], h1, wz);
        fma2(accN[0], h0, wn); fma2(accN[1], h1, wn);
    }

    const float* __restrict__ ig_t = g_IG + (size_t)t * B * H3;
    float2 bn = *(const float2*)&bias_n[col];

    #pragma unroll
    for (int rr = 0; rr < 2; rr++) {
        int row = row0 + 2 * r + rr;
        float2 hr = unpack2(accR[rr]);
        float2 hz = unpack2(accZ[rr]);
        float2 hn = unpack2(accN[rr]);
        const float* igrow = ig_t + (size_t)row * H3 + col;
        float2 ir  = *(const float2*)(igrow);
        float2 iz  = *(const float2*)(igrow + H);
        float2 inn = *(const float2*)(igrow + 2 * H);
        float2 hold = *(const float2*)&hs[(2 * r + rr) * H + col];

        float rx = sigmoidf_(ir.x + hr.x);
        float ry = sigmoidf_(ir.y + hr.y);
        float zx = sigmoidf_(iz.x + hz.x);
        float zy = sigmoidf_(iz.y + hz.y);
        float nx = tanhf_(inn.x + rx * (hn.x + bn.x));
        float ny = tanhf_(inn.y + ry * (hn.y + bn.y));
        float2 hnew;
        hnew.x = nx + zx * (hold.x - nx);
        hnew.y = ny + zy * (hold.y - ny);
        *(float2*)&h_out[(size_t)row * H + col] = hnew;
    }
}

// ---------------------------------------------------------------------------
// Final linear: out = h_final @ w_lin^T + bias_out. h_final lives in g_h[0]
// (512 steps: t=511 writes parity (511+1)&1 = 0).
// ---------------------------------------------------------------------------
__global__ __launch_bounds__(256) void final_linear(const float* __restrict__ bias_out,
                                                    float* __restrict__ out) {
    __shared__ float hsv[32 * H];   // 32 KB
    int tid = threadIdx.x;
    int row0 = blockIdx.x * 32;
    {
        const float4* src = (const float4*)(g_h[0] + (size_t)row0 * H);
        float4* dst = (float4*)hsv;
        #pragma unroll
        for (int i = 0; i < 8; i++) dst[tid + i * 256] = src[tid + i * 256];
    }
    __syncthreads();

    int c = tid & 31;   // 4 outputs: 4c..4c+3
    int r = tid >> 5;   // 4 rows: 4r..4r+3
    unsigned long long acc[4][2] = {};

    for (int k = 0; k < H; k++) {
        ulonglong2 w = *(const ulonglong2*)&g_WLt[k * OUT + 4 * c];  // LDG.128
        #pragma unroll
        for (int i = 0; i < 4; i++) {
            unsigned long long hv = bcast2(hsv[(4 * r + i) * H + k]);
            fma2(acc[i][0], hv, w.x);
            fma2(acc[i][1], hv, w.y);
        }
    }
    float b0 = bias_out[4 * c + 0];
    float b1 = bias_out[4 * c + 1];
    float b2 = bias_out[4 * c + 2];
    float b3 = bias_out[4 * c + 3];
    #pragma unroll
    for (int i = 0; i < 4; i++) {
        int row = row0 + 4 * r + i;
        float2 lo = unpack2(acc[i][0]);
        float2 hi = unpack2(acc[i][1]);
        float4 v = make_float4(lo.x + b0, lo.y + b1, hi.x + b2, hi.y + b3);
        *(float4*)&out[(size_t)row * OUT + 4 * c] = v;
    }
}

// ---------------------------------------------------------------------------
// Launch: prep -> IG GEMM -> 512 step kernels (graph serializes) -> linear
// ---------------------------------------------------------------------------
extern "C" void kernel_launch(void* const* d_in, const int* in_sizes, int n_in,
                              void* d_out, int out_size) {
    const float* x        = (const float*)d_in[0];
    const float* w_ih     = (const float*)d_in[1];
    const float* w_hh     = (const float*)d_in[2];
    const float* bias_g   = (const float*)d_in[3];
    const float* bias_n   = (const float*)d_in[4];
    const float* w_lin    = (const float*)d_in[5];
    const float* bias_out = (const float*)d_in[6];
    float* out = (float*)d_out;
    (void)x; (void)in_sizes; (void)n_in; (void)out_size;

    prep_kernel<<<768, 256>>>(w_ih, w_hh, w_lin);

    dim3 gIG(H3 / 64, BT / 32);            // (12, 8192)
    ig_gemm<<<gIG, 256>>>(x, bias_g);

    dim3 gStep(H / 32, B / 32);            // (8, 16) = 128 CTAs
    for (int t = 0; t < T; t++) {
        gru_step<<<gStep, 256>>>(t, bias_n);
    }

    final_linear<<<B / 32, 256>>>(bias_out, out);
}

// round 3
// speedup vs baseline: 1.9628x; 1.9628x over previous
#include <cuda_runtime.h>
#include <cstdint>
#include <cstddef>

// Problem dims
#define B   512
#define T   512
#define IN  128
#define H   256
#define H3  768
#define OUT 128
#define BT  (B * T)

// Step-kernel tiling
#define NCT    8      // column tiles over H (256/32)
#define CTILE  32     // h-cols per tile
#define GC     96     // gate cols per tile (3 * CTILE)
#define CHUNK  64     // k per async chunk
#define NCHUNK 4      // 256 / 64

// dynamic smem: 2 W buffers + duplicated-h
#define WBUF_BYTES  (2 * CHUNK * GC * 4)        // 49152
#define HS_BYTES    (H * 33 * 8)                // 67584
#define SMEM_STEP   (WBUF_BYTES + HS_BYTES)     // 116736

// ---------------------------------------------------------------------------
// Static device scratch (module-load allocation, permitted)
// ---------------------------------------------------------------------------
__device__ float g_IG[(size_t)BT * H3];                 // input gates [t][b][j]
__device__ float g_WihT[IN * H3];                       // W_ih^T [k][j]
__device__ __align__(16) float g_Wpack[NCT * H * GC];   // W_hh packed [ct][k][gc]
__device__ float g_WLt[H * OUT];                        // w_lin^T [k][o]
__device__ __align__(16) float g_h[2][B * H];           // ping-pong hidden state

// ---------------------------------------------------------------------------
// helpers
// ---------------------------------------------------------------------------
__device__ __forceinline__ void fma2(unsigned long long &acc,
                                     unsigned long long a,
                                     unsigned long long b) {
    asm("fma.rn.f32x2 %0, %1, %2, %0;" : "+l"(acc) : "l"(a), "l"(b));
}
__device__ __forceinline__ unsigned long long dup2(float x) {
    unsigned long long r;
    asm("mov.b64 %0, {%1, %1};" : "=l"(r) : "f"(x));
    return r;
}
__device__ __forceinline__ float2 unpack2(unsigned long long v) {
    float2 f;
    asm("mov.b64 {%0, %1}, %2;" : "=f"(f.x), "=f"(f.y) : "l"(v));
    return f;
}
__device__ __forceinline__ void cp16(uint32_t s, const void* g) {
    asm volatile("cp.async.cg.shared.global [%0], [%1], 16;" :: "r"(s), "l"(g));
}
__device__ __forceinline__ void cp_commit() {
    asm volatile("cp.async.commit_group;");
}
__device__ __forceinline__ void cp_wait0() {
    asm volatile("cp.async.wait_group 0;");
}

__device__ __forceinline__ float sigmoidf_(float x) {
    return __fdividef(1.0f, 1.0f + __expf(-x));
}
__device__ __forceinline__ float tanhf_(float x) {
    return __fdividef(2.0f, 1.0f + __expf(-2.0f * x)) - 1.0f;
}

// ---------------------------------------------------------------------------
// Prep: transposes + W_hh packing + h0 zero. One-shot, tiny.
// ---------------------------------------------------------------------------
__global__ void prep_kernel(const float* __restrict__ w_ih,
                            const float* __restrict__ w_hh,
                            const float* __restrict__ w_lin) {
    int i = blockIdx.x * blockDim.x + threadIdx.x;
    if (i < IN * H3) {                       // w_ih: (H3, IN) -> [k][j]
        int j = i / IN, k = i % IN;
        g_WihT[k * H3 + j] = w_ih[i];
    }
    if (i < NCT * H * GC) {                  // w_hh: (H3, H) -> [ct][k][g*32+cc]
        int gc = i % GC;
        int k  = (i / GC) % H;
        int ct = i / (GC * H);
        int g  = gc / CTILE, cc = gc % CTILE;
        g_Wpack[i] = w_hh[(g * H + ct * CTILE + cc) * H + k];
    }
    if (i < OUT * H) {                       // w_lin: (OUT, H) -> [k][o]
        int o = i / H, k = i % H;
        g_WLt[k * OUT + o] = w_lin[i];
    }
    if (i < B * H) g_h[0][i] = 0.0f;
}

// ---------------------------------------------------------------------------
// IG GEMM: g_IG[t][b][j] = x[b][t][:] . w_ih[j][:] + bias_g[j]
// ---------------------------------------------------------------------------
__global__ __launch_bounds__(256) void ig_gemm(const float* __restrict__ x,
                                               const float* __restrict__ bias_g) {
    __shared__ float Xs[32 * IN];
    __shared__ float Ws[IN * 64];
    int tid = threadIdx.x;
    int bt0 = blockIdx.y * 32;
    int j0  = blockIdx.x * 64;

    {
        const float4* src = (const float4*)(x + (size_t)bt0 * IN);
        float4* dst = (float4*)Xs;
        #pragma unroll
        for (int i = 0; i < 4; i++) dst[tid + i * 256] = src[tid + i * 256];
    }
    {
        #pragma unroll
        for (int i = 0; i < 8; i++) {
            int f = tid + i * 256;
            int k = f >> 4, j4 = (f & 15) << 2;
            *(float4*)&Ws[k * 64 + j4] =
                *(const float4*)&g_WihT[k * H3 + j0 + j4];
        }
    }
    __syncthreads();

    int c = tid & 15;
    int r = tid >> 4;
    unsigned long long acc[2][2] = {{0ULL, 0ULL}, {0ULL, 0ULL}};

    #pragma unroll 4
    for (int k = 0; k < IN; k++) {
        float x0 = Xs[(2 * r) * IN + k];
        float x1 = Xs[(2 * r + 1) * IN + k];
        ulonglong2 w = *(const ulonglong2*)&Ws[k * 64 + 4 * c];
        unsigned long long px0 = dup2(x0), px1 = dup2(x1);
        fma2(acc[0][0], px0, w.x); fma2(acc[0][1], px0, w.y);
        fma2(acc[1][0], px1, w.x); fma2(acc[1][1], px1, w.y);
    }

    float bg0 = bias_g[j0 + 4 * c + 0];
    float bg1 = bias_g[j0 + 4 * c + 1];
    float bg2 = bias_g[j0 + 4 * c + 2];
    float bg3 = bias_g[j0 + 4 * c + 3];
    #pragma unroll
    for (int rr = 0; rr < 2; rr++) {
        int bt = bt0 + 2 * r + rr;
        int b = bt >> 9;
        int t = bt & (T - 1);
        float2 lo = unpack2(acc[rr][0]);
        float2 hi = unpack2(acc[rr][1]);
        float4 out = make_float4(lo.x + bg0, lo.y + bg1, hi.x + bg2, hi.y + bg3);
        *(float4*)&g_IG[((size_t)t * B + b) * H3 + j0 + 4 * c] = out;
    }
}

// ---------------------------------------------------------------------------
// One GRU timestep. Tile 32 batch rows x 32 h-cols. 256 threads:
// thread = 1 row x 4 cols x 3 gates. W staged via cp.async double buffer,
// h staged as duplicated (h,h) u64 pairs (zero-MOV f32x2 broadcasts).
// ---------------------------------------------------------------------------
__global__ __launch_bounds__(256) void gru_step(int t, const float* __restrict__ bias_n) {
    extern __shared__ __align__(16) unsigned char smem_raw[];
    float* Wbuf = (float*)smem_raw;                                        // 2*CHUNK*GC
    unsigned long long* hs = (unsigned long long*)(smem_raw + WBUF_BYTES); // [k*33+row]

    const int tid  = threadIdx.x;
    const int r    = tid >> 3;       // row in tile, 0..31
    const int c    = tid & 7;        // 4-col group, 0..7
    const int j0   = blockIdx.x * CTILE;
    const int row0 = blockIdx.y * 32;

    const float* __restrict__ h_in  = g_h[t & 1];
    float* __restrict__ h_out       = g_h[(t + 1) & 1];
    const float* __restrict__ wsrc  = g_Wpack + (size_t)blockIdx.x * H * GC;

    uint32_t wbuf_s = (uint32_t)__cvta_generic_to_shared(Wbuf);

    // Prologue: async-load W chunk 0 into buffer 0
    {
        const float4* src = (const float4*)wsrc;
        #pragma unroll
        for (int j = 0; j < 6; j++) {
            int f = tid + j * 256;
            cp16(wbuf_s + f * 16, src + f);
        }
        cp_commit();
    }

    // Stage h tile as duplicated u64 pairs: hs[k*33 + row] = (h,h)
    {
        const int srow = tid >> 3;
        const int kb   = (tid & 7) * 4;
        const float* hp = h_in + (size_t)(row0 + srow) * H;
        #pragma unroll
        for (int i = 0; i < 8; i++) {
            int k4 = kb + i * 32;
            float4 v = *(const float4*)(hp + k4);
            hs[(k4 + 0) * 33 + srow] = dup2(v.x);
            hs[(k4 + 1) * 33 + srow] = dup2(v.y);
            hs[(k4 + 2) * 33 + srow] = dup2(v.z);
            hs[(k4 + 3) * 33 + srow] = dup2(v.w);
        }
    }

    unsigned long long accR0 = 0, accR1 = 0;
    unsigned long long accZ0 = 0, accZ1 = 0;
    unsigned long long accN0 = 0, accN1 = 0;

    for (int ch = 0; ch < NCHUNK; ch++) {
        cp_wait0();
        __syncthreads();          // chunk ch landed; also orders h staging (ch=0)
                                  // and guards buffer reuse (ch>0)
        if (ch + 1 < NCHUNK) {
            uint32_t dst = wbuf_s + ((ch + 1) & 1) * (CHUNK * GC * 4);
            const float4* src = (const float4*)(wsrc + (size_t)(ch + 1) * CHUNK * GC);
            #pragma unroll
            for (int j = 0; j < 6; j++) {
                int f = tid + j * 256;
                cp16(dst + f * 16, src + f);
            }
            cp_commit();
        }

        const float* Wb = Wbuf + (ch & 1) * (CHUNK * GC);
        const unsigned long long* hb = hs + (size_t)ch * CHUNK * 33;

        #pragma unroll 8
        for (int kk = 0; kk < CHUNK; kk++) {
            unsigned long long hd = hb[kk * 33 + r];                 // (h,h) pair
            const float* wp = Wb + kk * GC + 4 * c;
            ulonglong2 wR = *(const ulonglong2*)(wp);                // 4 cols, gate r
            ulonglong2 wZ = *(const ulonglong2*)(wp + 32);           // gate z
            ulonglong2 wN = *(const ulonglong2*)(wp + 64);           // gate n
            fma2(accR0, hd, wR.x); fma2(accR1, hd, wR.y);
            fma2(accZ0, hd, wZ.x); fma2(accZ1, hd, wZ.y);
            fma2(accN0, hd, wN.x); fma2(accN1, hd, wN.y);
        }
    }

    // Epilogue: gates for 4 columns of one row
    const int row = row0 + r;
    const int col = j0 + 4 * c;
    const float* igp = g_IG + ((size_t)t * B + row) * H3 + col;
    float4 ir  = *(const float4*)(igp);
    float4 iz  = *(const float4*)(igp + H);
    float4 inn = *(const float4*)(igp + 2 * H);
    float4 bn  = *(const float4*)(bias_n + col);
    float4 hold = *(const float4*)(h_in + (size_t)row * H + col);

    float2 hr0 = unpack2(accR0), hr1 = unpack2(accR1);
    float2 hz0 = unpack2(accZ0), hz1 = unpack2(accZ1);
    float2 hn0 = unpack2(accN0), hn1 = unpack2(accN1);

    float rg[4], zg[4], ho[4], ig_n[4], bnv[4], hnv[4];
    rg[0] = ir.x + hr0.x; rg[1] = ir.y + hr0.y; rg[2] = ir.z + hr1.x; rg[3] = ir.w + hr1.y;
    zg[0] = iz.x + hz0.x; zg[1] = iz.y + hz0.y; zg[2] = iz.z + hz1.x; zg[3] = iz.w + hz1.y;
    ig_n[0] = inn.x; ig_n[1] = inn.y; ig_n[2] = inn.z; ig_n[3] = inn.w;
    hnv[0] = hn0.x; hnv[1] = hn0.y; hnv[2] = hn1.x; hnv[3] = hn1.y;
    bnv[0] = bn.x; bnv[1] = bn.y; bnv[2] = bn.z; bnv[3] = bn.w;
    ho[0] = hold.x; ho[1] = hold.y; ho[2] = hold.z; ho[3] = hold.w;

    float outv[4];
    #pragma unroll
    for (int i = 0; i < 4; i++) {
        float rv = sigmoidf_(rg[i]);
        float zv = sigmoidf_(zg[i]);
        float nv = tanhf_(ig_n[i] + rv * (hnv[i] + bnv[i]));
        outv[i] = nv + zv * (ho[i] - nv);
    }
    *(float4*)&h_out[(size_t)row * H + col] =
        make_float4(outv[0], outv[1], outv[2], outv[3]);
}

// ---------------------------------------------------------------------------
// Final linear: out = h_final @ w_lin^T + bias_out (h_final in g_h[0])
// ---------------------------------------------------------------------------
__global__ __launch_bounds__(256) void final_linear(const float* __restrict__ bias_out,
                                                    float* __restrict__ out) {
    __shared__ float hsv[32 * H];
    int tid = threadIdx.x;
    int row0 = blockIdx.x * 32;
    {
        const float4* src = (const float4*)(g_h[0] + (size_t)row0 * H);
        float4* dst = (float4*)hsv;
        #pragma unroll
        for (int i = 0; i < 8; i++) dst[tid + i * 256] = src[tid + i * 256];
    }
    __syncthreads();

    int c = tid & 31;
    int r = tid >> 5;
    unsigned long long acc[4][2] = {};

    for (int k = 0; k < H; k++) {
        ulonglong2 w = *(const ulonglong2*)&g_WLt[k * OUT + 4 * c];
        #pragma unroll
        for (int i = 0; i < 4; i++) {
            unsigned long long hv = dup2(hsv[(4 * r + i) * H + k]);
            fma2(acc[i][0], hv, w.x);
            fma2(acc[i][1], hv, w.y);
        }
    }
    float b0 = bias_out[4 * c + 0];
    float b1 = bias_out[4 * c + 1];
    float b2 = bias_out[4 * c + 2];
    float b3 = bias_out[4 * c + 3];
    #pragma unroll
    for (int i = 0; i < 4; i++) {
        int row = row0 + 4 * r + i;
        float2 lo = unpack2(acc[i][0]);
        float2 hi = unpack2(acc[i][1]);
        float4 v = make_float4(lo.x + b0, lo.y + b1, hi.x + b2, hi.y + b3);
        *(float4*)&out[(size_t)row * OUT + 4 * c] = v;
    }
}

// ---------------------------------------------------------------------------
// Launch
// ---------------------------------------------------------------------------
extern "C" void kernel_launch(void* const* d_in, const int* in_sizes, int n_in,
                              void* d_out, int out_size) {
    const float* x        = (const float*)d_in[0];
    const float* w_ih     = (const float*)d_in[1];
    const float* w_hh     = (const float*)d_in[2];
    const float* bias_g   = (const float*)d_in[3];
    const float* bias_n   = (const float*)d_in[4];
    const float* w_lin    = (const float*)d_in[5];
    const float* bias_out = (const float*)d_in[6];
    float* out = (float*)d_out;
    (void)in_sizes; (void)n_in; (void)out_size;

    (void)cudaFuncSetAttribute(gru_step,
                               cudaFuncAttributeMaxDynamicSharedMemorySize,
                               SMEM_STEP);

    prep_kernel<<<768, 256>>>(w_ih, w_hh, w_lin);

    dim3 gIG(H3 / 64, BT / 32);            // (12, 8192)
    ig_gemm<<<gIG, 256>>>(x, bias_g);

    dim3 gStep(NCT, B / 32);               // (8, 16) = 128 CTAs
    for (int t = 0; t < T; t++) {
        gru_step<<<gStep, 256, SMEM_STEP>>>(t, bias_n);
    }

    final_linear<<<B / 32, 256>>>(bias_out, out);
}

// round 4
// speedup vs baseline: 2.4313x; 1.2387x over previous
#include <cuda_runtime.h>
#include <cstdint>
#include <cstddef>

// Problem dims
#define B   512
#define T   512
#define IN  128
#define H   256
#define H3  768
#define OUT 128
#define BT  (B * T)

// Step-kernel tiling
#define NCT    8      // column tiles over H (256/32)
#define CTILE  32     // h-cols per tile
#define GC     96     // gate cols per tile (3 * CTILE)
#define CHUNK  64     // k per async chunk
#define NCHUNK 4      // 256 / 64

// gru_step dynamic smem: 2 W buffers + plain h tile [row][k]
#define WBUF_BYTES  (2 * CHUNK * GC * 4)        // 49152
#define HS_BYTES    (32 * H * 4)                // 32768
#define SMEM_STEP   (WBUF_BYTES + HS_BYTES)     // 81920

// ig_gemm dynamic smem: X 64x128 + W 128x64
#define IG_XS_BYTES (64 * IN * 4)               // 32768
#define IG_WS_BYTES (IN * 64 * 4)               // 32768
#define SMEM_IG     (IG_XS_BYTES + IG_WS_BYTES) // 65536

// ---------------------------------------------------------------------------
// Static device scratch (module-load allocation, permitted)
// ---------------------------------------------------------------------------
__device__ float g_IG[(size_t)BT * H3];                 // input gates [t][b][j]
__device__ float g_WihT[IN * H3];                       // W_ih^T [k][j]
__device__ __align__(16) float g_Wpack[NCT * H * GC];   // W_hh packed [ct][k][gc]
__device__ float g_WLt[H * OUT];                        // w_lin^T [k][o]
__device__ __align__(16) float g_h[2][B * H];           // ping-pong hidden state

// ---------------------------------------------------------------------------
// helpers
// ---------------------------------------------------------------------------
__device__ __forceinline__ void fma2(unsigned long long &acc,
                                     unsigned long long a,
                                     unsigned long long b) {
    asm("fma.rn.f32x2 %0, %1, %2, %0;" : "+l"(acc) : "l"(a), "l"(b));
}
__device__ __forceinline__ unsigned long long dup2(float x) {
    unsigned long long r;
    asm("mov.b64 %0, {%1, %1};" : "=l"(r) : "f"(x));
    return r;
}
__device__ __forceinline__ float2 unpack2(unsigned long long v) {
    float2 f;
    asm("mov.b64 {%0, %1}, %2;" : "=f"(f.x), "=f"(f.y) : "l"(v));
    return f;
}
__device__ __forceinline__ void cp16(uint32_t s, const void* g) {
    asm volatile("cp.async.cg.shared.global [%0], [%1], 16;" :: "r"(s), "l"(g));
}
__device__ __forceinline__ void cp_commit() {
    asm volatile("cp.async.commit_group;");
}
__device__ __forceinline__ void cp_wait0() {
    asm volatile("cp.async.wait_group 0;");
}

__device__ __forceinline__ float sigmoidf_(float x) {
    return __fdividef(1.0f, 1.0f + __expf(-x));
}
__device__ __forceinline__ float tanhf_(float x) {
    return __fdividef(2.0f, 1.0f + __expf(-2.0f * x)) - 1.0f;
}

// ---------------------------------------------------------------------------
// Prep: transposes + W_hh packing + h0 zero. One-shot, tiny.
// ---------------------------------------------------------------------------
__global__ void prep_kernel(const float* __restrict__ w_ih,
                            const float* __restrict__ w_hh,
                            const float* __restrict__ w_lin) {
    int i = blockIdx.x * blockDim.x + threadIdx.x;
    if (i < IN * H3) {                       // w_ih: (H3, IN) -> [k][j]
        int j = i / IN, k = i % IN;
        g_WihT[k * H3 + j] = w_ih[i];
    }
    if (i < NCT * H * GC) {                  // w_hh: (H3, H) -> [ct][k][g*32+cc]
        int gc = i % GC;
        int k  = (i / GC) % H;
        int ct = i / (GC * H);
        int g  = gc / CTILE, cc = gc % CTILE;
        g_Wpack[i] = w_hh[(g * H + ct * CTILE + cc) * H + k];
    }
    if (i < OUT * H) {                       // w_lin: (OUT, H) -> [k][o]
        int o = i / H, k = i % H;
        g_WLt[k * OUT + o] = w_lin[i];
    }
    if (i < B * H) g_h[0][i] = 0.0f;
}

// ---------------------------------------------------------------------------
// IG GEMM: g_IG[t][b][j] = x[b][t][:] . w_ih[j][:] + bias_g[j]
// Tile 64 bt-rows x 64 j-cols, K=128. 256 threads, thread = 4 rows x 4 cols.
// ---------------------------------------------------------------------------
__global__ __launch_bounds__(256) void ig_gemm(const float* __restrict__ x,
                                               const float* __restrict__ bias_g) {
    extern __shared__ __align__(16) unsigned char ig_smem[];
    float* Xs = (float*)ig_smem;                     // [row][k] 64x128
    float* Ws = (float*)(ig_smem + IG_XS_BYTES);     // [k][j]   128x64

    int tid = threadIdx.x;
    int bt0 = blockIdx.y * 64;
    int j0  = blockIdx.x * 64;

    // Load X tile (64x128 contiguous floats) — coalesced float4 copy
    {
        const float4* src = (const float4*)(x + (size_t)bt0 * IN);
        float4* dst = (float4*)Xs;
        #pragma unroll
        for (int i = 0; i < 8; i++) dst[tid + i * 256] = src[tid + i * 256];
    }
    // Load W tile from pre-transposed g_WihT: rows k, cols j0..j0+63
    {
        #pragma unroll
        for (int i = 0; i < 8; i++) {
            int f = tid + i * 256;
            int k = f >> 4, j4 = (f & 15) << 2;
            *(float4*)&Ws[k * 64 + j4] =
                *(const float4*)&g_WihT[k * H3 + j0 + j4];
        }
    }
    __syncthreads();

    int c = tid & 15;   // 4 cols: 4c..4c+3
    int r = tid >> 4;   // 4 rows: 4r..4r+3
    unsigned long long acc[4][2] = {};

    #pragma unroll 2
    for (int k4 = 0; k4 < IN; k4 += 4) {
        float xv[4][4];
        #pragma unroll
        for (int i = 0; i < 4; i++)
            *(float4*)xv[i] = *(const float4*)&Xs[(4 * r + i) * IN + k4];
        #pragma unroll
        for (int kk = 0; kk < 4; kk++) {
            ulonglong2 w = *(const ulonglong2*)&Ws[(k4 + kk) * 64 + 4 * c];
            #pragma unroll
            for (int i = 0; i < 4; i++) {
                unsigned long long xd = dup2(xv[i][kk]);
                fma2(acc[i][0], xd, w.x);
                fma2(acc[i][1], xd, w.y);
            }
        }
    }

    float bg0 = bias_g[j0 + 4 * c + 0];
    float bg1 = bias_g[j0 + 4 * c + 1];
    float bg2 = bias_g[j0 + 4 * c + 2];
    float bg3 = bias_g[j0 + 4 * c + 3];
    #pragma unroll
    for (int i = 0; i < 4; i++) {
        int bt = bt0 + 4 * r + i;
        int b = bt >> 9;          // bt = b*T + t, T = 512
        int t = bt & (T - 1);
        float2 lo = unpack2(acc[i][0]);
        float2 hi = unpack2(acc[i][1]);
        float4 o = make_float4(lo.x + bg0, lo.y + bg1, hi.x + bg2, hi.y + bg3);
        *(float4*)&g_IG[((size_t)t * B + b) * H3 + j0 + 4 * c] = o;
    }
}

// ---------------------------------------------------------------------------
// One GRU timestep. Tile 32 batch rows x 32 h-cols. 512 threads (4 warps/SMSP):
// thread = 1 row x 2 cols x 3 gates. W via cp.async double buffer (LDS.64),
// h via plain [row][k] smem: 1 LDS.128 per 4k + register mov.b64 duplication.
// ---------------------------------------------------------------------------
__global__ __launch_bounds__(512) void gru_step(int t, const float* __restrict__ bias_n) {
    extern __shared__ __align__(16) unsigned char smem_raw[];
    float* Wbuf = (float*)smem_raw;                        // 2 * CHUNK * GC
    float* hs   = (float*)(smem_raw + WBUF_BYTES);         // [row][k] 32x256

    const int tid  = threadIdx.x;
    const int r    = tid >> 4;       // row in tile, 0..31
    const int c    = tid & 15;       // colpair, 0..15
    const int j0   = blockIdx.x * CTILE;
    const int row0 = blockIdx.y * 32;

    const float* __restrict__ h_in  = g_h[t & 1];
    float* __restrict__ h_out       = g_h[(t + 1) & 1];
    const float* __restrict__ wsrc  = g_Wpack + (size_t)blockIdx.x * H * GC;

    uint32_t wbuf_s = (uint32_t)__cvta_generic_to_shared(Wbuf);

    // Prefetch epilogue operands (g_IG is DRAM-resident; hide under k-loop)
    const int row = row0 + r;
    const int col = j0 + 2 * c;
    const float* igp = g_IG + ((size_t)t * B + row) * H3 + col;
    float2 ir  = *(const float2*)(igp);
    float2 iz  = *(const float2*)(igp + H);
    float2 inn = *(const float2*)(igp + 2 * H);
    float2 bn  = *(const float2*)(bias_n + col);

    // Prologue: async-load W chunk 0 into buffer 0 (24576 B / 16 / 512 = 3 each)
    {
        const float4* src = (const float4*)wsrc;
        #pragma unroll
        for (int j = 0; j < 3; j++) {
            int f = tid + j * 512;
            cp16(wbuf_s + f * 16, src + f);
        }
        cp_commit();
    }

    // Stage h tile (32x256 contiguous) — coalesced float4 copy
    {
        const float4* src = (const float4*)(h_in + (size_t)row0 * H);
        float4* dst = (float4*)hs;
        #pragma unroll
        for (int i = 0; i < 4; i++) dst[tid + i * 512] = src[tid + i * 512];
    }

    unsigned long long aR = 0, aZ = 0, aN = 0;
    const float4* hrow = (const float4*)(hs + r * H);

    for (int ch = 0; ch < NCHUNK; ch++) {
        cp_wait0();
        __syncthreads();          // chunk ch landed; orders h staging (ch=0)
                                  // and guards buffer reuse (ch>0)
        if (ch + 1 < NCHUNK) {
            uint32_t dst = wbuf_s + ((ch + 1) & 1) * (CHUNK * GC * 4);
            const float4* src = (const float4*)(wsrc + (size_t)(ch + 1) * CHUNK * GC);
            #pragma unroll
            for (int j = 0; j < 3; j++) {
                int f = tid + j * 512;
                cp16(dst + f * 16, src + f);
            }
            cp_commit();
        }

        const float* Wb = Wbuf + (ch & 1) * (CHUNK * GC);
        const int kbase4 = ch * (CHUNK / 4);

        #pragma unroll 2
        for (int k8 = 0; k8 < CHUNK; k8 += 8) {
            float4 ha = hrow[kbase4 + (k8 >> 2)];
            float4 hb = hrow[kbase4 + (k8 >> 2) + 1];
            unsigned long long hd[8];
            hd[0] = dup2(ha.x); hd[1] = dup2(ha.y);
            hd[2] = dup2(ha.z); hd[3] = dup2(ha.w);
            hd[4] = dup2(hb.x); hd[5] = dup2(hb.y);
            hd[6] = dup2(hb.z); hd[7] = dup2(hb.w);
            #pragma unroll
            for (int i = 0; i < 8; i++) {
                const float* wp = Wb + (k8 + i) * GC + 2 * c;
                fma2(aR, hd[i], *(const unsigned long long*)(wp));
                fma2(aZ, hd[i], *(const unsigned long long*)(wp + 32));
                fma2(aN, hd[i], *(const unsigned long long*)(wp + 64));
            }
        }
    }

    // Epilogue: gates for 2 columns of one row
    float2 hr = unpack2(aR);
    float2 hz = unpack2(aZ);
    float2 hn = unpack2(aN);
    float2 hold = *(const float2*)&hs[r * H + col];   // h_old from smem

    float rx = sigmoidf_(ir.x + hr.x);
    float ry = sigmoidf_(ir.y + hr.y);
    float zx = sigmoidf_(iz.x + hz.x);
    float zy = sigmoidf_(iz.y + hz.y);
    float nx = tanhf_(inn.x + rx * (hn.x + bn.x));
    float ny = tanhf_(inn.y + ry * (hn.y + bn.y));
    float2 hnew;
    hnew.x = nx + zx * (hold.x - nx);
    hnew.y = ny + zy * (hold.y - ny);
    *(float2*)&h_out[(size_t)row * H + col] = hnew;
}

// ---------------------------------------------------------------------------
// Final linear: out = h_final @ w_lin^T + bias_out (h_final in g_h[0])
// ---------------------------------------------------------------------------
__global__ __launch_bounds__(256) void final_linear(const float* __restrict__ bias_out,
                                                    float* __restrict__ out) {
    __shared__ float hsv[32 * H];
    int tid = threadIdx.x;
    int row0 = blockIdx.x * 32;
    {
        const float4* src = (const float4*)(g_h[0] + (size_t)row0 * H);
        float4* dst = (float4*)hsv;
        #pragma unroll
        for (int i = 0; i < 8; i++) dst[tid + i * 256] = src[tid + i * 256];
    }
    __syncthreads();

    int c = tid & 31;
    int r = tid >> 5;
    unsigned long long acc[4][2] = {};

    for (int k = 0; k < H; k++) {
        ulonglong2 w = *(const ulonglong2*)&g_WLt[k * OUT + 4 * c];
        #pragma unroll
        for (int i = 0; i < 4; i++) {
            unsigned long long hv = dup2(hsv[(4 * r + i) * H + k]);
            fma2(acc[i][0], hv, w.x);
            fma2(acc[i][1], hv, w.y);
        }
    }
    float b0 = bias_out[4 * c + 0];
    float b1 = bias_out[4 * c + 1];
    float b2 = bias_out[4 * c + 2];
    float b3 = bias_out[4 * c + 3];
    #pragma unroll
    for (int i = 0; i < 4; i++) {
        int row = row0 + 4 * r + i;
        float2 lo = unpack2(acc[i][0]);
        float2 hi = unpack2(acc[i][1]);
        float4 v = make_float4(lo.x + b0, lo.y + b1, hi.x + b2, hi.y + b3);
        *(float4*)&out[(size_t)row * OUT + 4 * c] = v;
    }
}

// ---------------------------------------------------------------------------
// Launch
// ---------------------------------------------------------------------------
extern "C" void kernel_launch(void* const* d_in, const int* in_sizes, int n_in,
                              void* d_out, int out_size) {
    const float* x        = (const float*)d_in[0];
    const float* w_ih     = (const float*)d_in[1];
    const float* w_hh     = (const float*)d_in[2];
    const float* bias_g   = (const float*)d_in[3];
    const float* bias_n   = (const float*)d_in[4];
    const float* w_lin    = (const float*)d_in[5];
    const float* bias_out = (const float*)d_in[6];
    float* out = (float*)d_out;
    (void)in_sizes; (void)n_in; (void)out_size;

    (void)cudaFuncSetAttribute(gru_step,
                               cudaFuncAttributeMaxDynamicSharedMemorySize,
                               SMEM_STEP);
    (void)cudaFuncSetAttribute(ig_gemm,
                               cudaFuncAttributeMaxDynamicSharedMemorySize,
                               SMEM_IG);

    prep_kernel<<<768, 256>>>(w_ih, w_hh, w_lin);

    dim3 gIG(H3 / 64, BT / 64);            // (12, 4096)
    ig_gemm<<<gIG, 256, SMEM_IG>>>(x, bias_g);

    dim3 gStep(NCT, B / 32);               // (8, 16) = 128 CTAs
    for (int t = 0; t < T; t++) {
        gru_step<<<gStep, 512, SMEM_STEP>>>(t, bias_n);
    }

    final_linear<<<B / 32, 256>>>(bias_out, out);
}

// round 7
// speedup vs baseline: 2.4859x; 1.0224x over previous
#include <cuda_runtime.h>
#include <cstdint>
#include <cstddef>

// Problem dims
#define B   512
#define T   512
#define IN  128
#define H   256
#define H3  768
#define OUT 128
#define BT  (B * T)

// Step-kernel tiling
#define NCT    8      // column tiles over H (256/32)
#define CTILE  32     // h-cols per tile
#define GC     96     // gate cols per tile (3 * CTILE)
#define CHUNK  64     // k per async chunk
#define NCHUNK 4      // 256 / 64

// gru_step dynamic smem: 2 W buffers + padded h tile  (< 128 KiB)
#define WBUF_BYTES  (2 * CHUNK * GC * 4)        // 49152
#define HROW_PAD    260                         // 256 + 4 floats (bank de-conflict)
#define HS_BYTES    (32 * HROW_PAD * 4)         // 33280
#define SMEM_STEP   (WBUF_BYTES + HS_BYTES)     // 82432

// ig_gemm dynamic smem: X 64x128 + W 128x64
#define IG_XS_BYTES (64 * IN * 4)               // 32768
#define IG_WS_BYTES (IN * 64 * 4)               // 32768
#define SMEM_IG     (IG_XS_BYTES + IG_WS_BYTES) // 65536

// ---------------------------------------------------------------------------
// Static device scratch (module-load allocation, permitted)
// ---------------------------------------------------------------------------
__device__ float g_IG[(size_t)BT * H3];                 // input gates [t][b][j]
__device__ float g_WihT[IN * H3];                       // W_ih^T [k][j]
__device__ __align__(16) float g_Wpack[NCT * H * GC];   // W_hh packed [ct][k][gc]
__device__ float g_WLt[H * OUT];                        // w_lin^T [k][o]
__device__ __align__(16) float g_h[2][B * H];           // ping-pong hidden state

// ---------------------------------------------------------------------------
// helpers
// ---------------------------------------------------------------------------
__device__ __forceinline__ void fma2(unsigned long long &acc,
                                     unsigned long long a,
                                     unsigned long long b) {
    asm("fma.rn.f32x2 %0, %1, %2, %0;" : "+l"(acc) : "l"(a), "l"(b));
}
__device__ __forceinline__ unsigned long long dup2(float x) {
    unsigned long long r;
    asm("mov.b64 %0, {%1, %1};" : "=l"(r) : "f"(x));
    return r;
}
__device__ __forceinline__ float2 unpack2(unsigned long long v) {
    float2 f;
    asm("mov.b64 {%0, %1}, %2;" : "=f"(f.x), "=f"(f.y) : "l"(v));
    return f;
}
__device__ __forceinline__ void cp16(uint32_t s, const void* g) {
    asm volatile("cp.async.cg.shared.global [%0], [%1], 16;" :: "r"(s), "l"(g));
}
__device__ __forceinline__ void cp_commit() {
    asm volatile("cp.async.commit_group;");
}
__device__ __forceinline__ void cp_wait0() {
    asm volatile("cp.async.wait_group 0;");
}

__device__ __forceinline__ float sigmoidf_(float x) {
    return __fdividef(1.0f, 1.0f + __expf(-x));
}
__device__ __forceinline__ float tanhf_(float x) {
    return __fdividef(2.0f, 1.0f + __expf(-2.0f * x)) - 1.0f;
}

// ---------------------------------------------------------------------------
// Prep: transposes + W_hh packing + h0 zero. One-shot, tiny.
// ---------------------------------------------------------------------------
__global__ void prep_kernel(const float* __restrict__ w_ih,
                            const float* __restrict__ w_hh,
                            const float* __restrict__ w_lin) {
    int i = blockIdx.x * blockDim.x + threadIdx.x;
    if (i < IN * H3) {                       // w_ih: (H3, IN) -> [k][j]
        int j = i / IN, k = i % IN;
        g_WihT[k * H3 + j] = w_ih[i];
    }
    if (i < NCT * H * GC) {                  // w_hh: (H3, H) -> [ct][k][g*32+cc]
        int gc = i % GC;
        int k  = (i / GC) % H;
        int ct = i / (GC * H);
        int g  = gc / CTILE, cc = gc % CTILE;
        g_Wpack[i] = w_hh[(g * H + ct * CTILE + cc) * H + k];
    }
    if (i < OUT * H) {                       // w_lin: (OUT, H) -> [k][o]
        int o = i / H, k = i % H;
        g_WLt[k * OUT + o] = w_lin[i];
    }
    if (i < B * H) g_h[0][i] = 0.0f;
}

// ---------------------------------------------------------------------------
// IG GEMM: g_IG[t][b][j] = x[b][t][:] . w_ih[j][:] + bias_g[j]
// Tile 64 bt-rows x 64 j-cols, K=128. 256 threads, thread = 4 rows x 4 cols.
// ---------------------------------------------------------------------------
__global__ __launch_bounds__(256) void ig_gemm(const float* __restrict__ x,
                                               const float* __restrict__ bias_g) {
    extern __shared__ __align__(16) unsigned char ig_smem[];
    float* Xs = (float*)ig_smem;                     // [row][k] 64x128
    float* Ws = (float*)(ig_smem + IG_XS_BYTES);     // [k][j]   128x64

    int tid = threadIdx.x;
    int bt0 = blockIdx.y * 64;
    int j0  = blockIdx.x * 64;

    {
        const float4* src = (const float4*)(x + (size_t)bt0 * IN);
        float4* dst = (float4*)Xs;
        #pragma unroll
        for (int i = 0; i < 8; i++) dst[tid + i * 256] = src[tid + i * 256];
    }
    {
        #pragma unroll
        for (int i = 0; i < 8; i++) {
            int f = tid + i * 256;
            int k = f >> 4, j4 = (f & 15) << 2;
            *(float4*)&Ws[k * 64 + j4] =
                *(const float4*)&g_WihT[k * H3 + j0 + j4];
        }
    }
    __syncthreads();

    int c = tid & 15;   // 4 cols: 4c..4c+3
    int r = tid >> 4;   // 4 rows: 4r..4r+3
    unsigned long long acc[4][2] = {};

    #pragma unroll 2
    for (int k4 = 0; k4 < IN; k4 += 4) {
        float xv[4][4];
        #pragma unroll
        for (int i = 0; i < 4; i++)
            *(float4*)xv[i] = *(const float4*)&Xs[(4 * r + i) * IN + k4];
        #pragma unroll
        for (int kk = 0; kk < 4; kk++) {
            ulonglong2 w = *(const ulonglong2*)&Ws[(k4 + kk) * 64 + 4 * c];
            #pragma unroll
            for (int i = 0; i < 4; i++) {
                unsigned long long xd = dup2(xv[i][kk]);
                fma2(acc[i][0], xd, w.x);
                fma2(acc[i][1], xd, w.y);
            }
        }
    }

    float bg0 = bias_g[j0 + 4 * c + 0];
    float bg1 = bias_g[j0 + 4 * c + 1];
    float bg2 = bias_g[j0 + 4 * c + 2];
    float bg3 = bias_g[j0 + 4 * c + 3];
    #pragma unroll
    for (int i = 0; i < 4; i++) {
        int bt = bt0 + 4 * r + i;
        int b = bt >> 9;          // bt = b*T + t, T = 512
        int t = bt & (T - 1);
        float2 lo = unpack2(acc[i][0]);
        float2 hi = unpack2(acc[i][1]);
        float4 o = make_float4(lo.x + bg0, lo.y + bg1, hi.x + bg2, hi.y + bg3);
        *(float4*)&g_IG[((size_t)t * B + b) * H3 + j0 + 4 * c] = o;
    }
}

// ---------------------------------------------------------------------------
// One GRU timestep. Tile 32 batch rows x 32 h-cols, 256 threads:
//   r = tid>>3 : row 0..31,  c = tid&7 : 4-col quad
// Thread = 1 row x 4 cols x 3 gates over all 256 k (6 u64 f32x2 accums).
// Warp = 4 rows x 8 quads: each W LDS.128 is a 128B broadcast wavefront.
// W streamed in 24KB cp.async double-buffered chunks; h in padded smem rows.
// ---------------------------------------------------------------------------
__global__ __launch_bounds__(256) void gru_step(int t, const float* __restrict__ bias_n) {
    extern __shared__ __align__(16) unsigned char smem_raw[];
    float* Wbuf = (float*)smem_raw;                        // 2 x [64][96]
    float* hs   = (float*)(smem_raw + WBUF_BYTES);         // [32][260]

    const int tid = threadIdx.x;
    const int r   = tid >> 3;        // row in tile
    const int c   = tid & 7;         // 4-col quad
    const int j0   = blockIdx.x * CTILE;
    const int row0 = blockIdx.y * 32;

    const float* __restrict__ h_in  = g_h[t & 1];
    float* __restrict__ h_out       = g_h[(t + 1) & 1];
    const float* __restrict__ wsrc  = g_Wpack + (size_t)blockIdx.x * H * GC;

    uint32_t wbuf_s = (uint32_t)__cvta_generic_to_shared(Wbuf);

    // Prologue: async-load W chunk 0 (24576 B; 6 x cp16 per thread)
    {
        const float4* src = (const float4*)wsrc;
        #pragma unroll
        for (int j = 0; j < 6; j++) {
            int f = tid + j * 256;
            cp16(wbuf_s + f * 16, src + f);
        }
        cp_commit();
    }

    // Prefetch epilogue operands (DRAM-resident IG), hidden under the k-loop
    const int row = row0 + r;
    const int col = j0 + 4 * c;
    const float* igp = g_IG + ((size_t)t * B + row) * H3 + col;
    float4 ir  = *(const float4*)(igp);
    float4 iz  = *(const float4*)(igp + H);
    float4 inn = *(const float4*)(igp + 2 * H);
    float4 bn  = *(const float4*)(bias_n + col);

    // Stage h tile into padded rows: hs[row][k], row stride 260 floats
    {
        const float4* src = (const float4*)(h_in + (size_t)row0 * H);
        #pragma unroll
        for (int i = 0; i < 8; i++) {
            int f = tid + i * 256;              // 0..2047 float4s
            int rr = f >> 6, k4 = f & 63;
            *(float4*)&hs[rr * HROW_PAD + k4 * 4] = src[f];
        }
    }

    unsigned long long aR0 = 0, aR1 = 0, aZ0 = 0, aZ1 = 0, aN0 = 0, aN1 = 0;
    const float4* hrow4 = (const float4*)(hs + r * HROW_PAD);

    for (int ch = 0; ch < NCHUNK; ch++) {
        cp_wait0();
        __syncthreads();          // chunk ch landed; orders h staging (ch=0)
                                  // and guards buffer reuse (ch>0)
        if (ch + 1 < NCHUNK) {
            uint32_t dst = wbuf_s + ((ch + 1) & 1) * (CHUNK * GC * 4);
            const float4* src = (const float4*)(wsrc + (size_t)(ch + 1) * CHUNK * GC);
            #pragma unroll
            for (int j = 0; j < 6; j++) {
                int f = tid + j * 256;
                cp16(dst + f * 16, src + f);
            }
            cp_commit();
        }

        const float* wbase = Wbuf + (ch & 1) * (CHUNK * GC) + 4 * c;
        const float4* hq = hrow4 + ch * (CHUNK / 4);

        #pragma unroll 4
        for (int k4i = 0; k4i < CHUNK / 4; k4i++) {    // 4 k's per iteration
            float4 hv = hq[k4i];
            unsigned long long hd[4];
            hd[0] = dup2(hv.x); hd[1] = dup2(hv.y);
            hd[2] = dup2(hv.z); hd[3] = dup2(hv.w);
            const float* wp = wbase + (k4i * 4) * GC;
            #pragma unroll
            for (int kk = 0; kk < 4; kk++) {
                ulonglong2 wR = *(const ulonglong2*)(wp);        // 128B bcast wf
                ulonglong2 wZ = *(const ulonglong2*)(wp + 32);
                ulonglong2 wN = *(const ulonglong2*)(wp + 64);
                fma2(aR0, hd[kk], wR.x); fma2(aR1, hd[kk], wR.y);
                fma2(aZ0, hd[kk], wZ.x); fma2(aZ1, hd[kk], wZ.y);
                fma2(aN0, hd[kk], wN.x); fma2(aN1, hd[kk], wN.y);
                wp += GC;
            }
        }
    }

    // Epilogue: gates for 4 columns of one row
    float2 hrA = unpack2(aR0), hrB = unpack2(aR1);
    float2 hzA = unpack2(aZ0), hzB = unpack2(aZ1);
    float2 hnA = unpack2(aN0), hnB = unpack2(aN1);
    float4 hold = *(const float4*)&hs[r * HROW_PAD + col];

    float rg[4] = {ir.x + hrA.x, ir.y + hrA.y, ir.z + hrB.x, ir.w + hrB.y};
    float zg[4] = {iz.x + hzA.x, iz.y + hzA.y, iz.z + hzB.x, iz.w + hzB.y};
    float hnv[4] = {hnA.x, hnA.y, hnB.x, hnB.y};
    float igv[4] = {inn.x, inn.y, inn.z, inn.w};
    float bnv[4] = {bn.x, bn.y, bn.z, bn.w};
    float hov[4] = {hold.x, hold.y, hold.z, hold.w};

    float outv[4];
    #pragma unroll
    for (int i = 0; i < 4; i++) {
        float rv = sigmoidf_(rg[i]);
        float zv = sigmoidf_(zg[i]);
        float nv = tanhf_(igv[i] + rv * (hnv[i] + bnv[i]));
        outv[i] = nv + zv * (hov[i] - nv);
    }
    *(float4*)&h_out[(size_t)row * H + col] =
        make_float4(outv[0], outv[1], outv[2], outv[3]);
}

// ---------------------------------------------------------------------------
// Final linear: out = h_final @ w_lin^T + bias_out (h_final in g_h[0])
// ---------------------------------------------------------------------------
__global__ __launch_bounds__(256) void final_linear(const float* __restrict__ bias_out,
                                                    float* __restrict__ out) {
    __shared__ float hsv[32 * H];
    int tid = threadIdx.x;
    int row0 = blockIdx.x * 32;
    {
        const float4* src = (const float4*)(g_h[0] + (size_t)row0 * H);
        float4* dst = (float4*)hsv;
        #pragma unroll
        for (int i = 0; i < 8; i++) dst[tid + i * 256] = src[tid + i * 256];
    }
    __syncthreads();

    int c = tid & 31;
    int r = tid >> 5;
    unsigned long long acc[4][2] = {};

    for (int k = 0; k < H; k++) {
        ulonglong2 w = *(const ulonglong2*)&g_WLt[k * OUT + 4 * c];
        #pragma unroll
        for (int i = 0; i < 4; i++) {
            unsigned long long hv = dup2(hsv[(4 * r + i) * H + k]);
            fma2(acc[i][0], hv, w.x);
            fma2(acc[i][1], hv, w.y);
        }
    }
    float b0 = bias_out[4 * c + 0];
    float b1 = bias_out[4 * c + 1];
    float b2 = bias_out[4 * c + 2];
    float b3 = bias_out[4 * c + 3];
    #pragma unroll
    for (int i = 0; i < 4; i++) {
        int row = row0 + 4 * r + i;
        float2 lo = unpack2(acc[i][0]);
        float2 hi = unpack2(acc[i][1]);
        float4 v = make_float4(lo.x + b0, lo.y + b1, hi.x + b2, hi.y + b3);
        *(float4*)&out[(size_t)row * OUT + 4 * c] = v;
    }
}

// ---------------------------------------------------------------------------
// Launch
// ---------------------------------------------------------------------------
extern "C" void kernel_launch(void* const* d_in, const int* in_sizes, int n_in,
                              void* d_out, int out_size) {
    const float* x        = (const float*)d_in[0];
    const float* w_ih     = (const float*)d_in[1];
    const float* w_hh     = (const float*)d_in[2];
    const float* bias_g   = (const float*)d_in[3];
    const float* bias_n   = (const float*)d_in[4];
    const float* w_lin    = (const float*)d_in[5];
    const float* bias_out = (const float*)d_in[6];
    float* out = (float*)d_out;
    (void)in_sizes; (void)n_in; (void)out_size;

    (void)cudaFuncSetAttribute(gru_step,
                               cudaFuncAttributeMaxDynamicSharedMemorySize,
                               SMEM_STEP);
    (void)cudaFuncSetAttribute(ig_gemm,
                               cudaFuncAttributeMaxDynamicSharedMemorySize,
                               SMEM_IG);

    prep_kernel<<<768, 256>>>(w_ih, w_hh, w_lin);

    dim3 gIG(H3 / 64, BT / 64);            // (12, 4096)
    ig_gemm<<<gIG, 256, SMEM_IG>>>(x, bias_g);

    dim3 gStep(NCT, B / 32);               // (8, 16) = 128 CTAs
    for (int t = 0; t < T; t++) {
        gru_step<<<gStep, 256, SMEM_STEP>>>(t, bias_n);
    }

    final_linear<<<B / 32, 256>>>(bias_out, out);
}